// round 1
// baseline (speedup 1.0000x reference)
#include <cuda_runtime.h>

#define NN 100000
#define NE 3200000
#define ET (NE + NN)
#define HH 32
#define EMBD 16

// ---------------- device scratch (static, no allocation) ----------------
__device__ float    g_sums[NN];
__device__ float    g_cnts[NN];
__device__ float    g_loop[NN];
__device__ float    g_h[NN * HH];
__device__ float    g_hs[NN];
__device__ float    g_hd[NN];
__device__ unsigned g_amax[NN];
__device__ float    g_den[NN];
__device__ float    g_alpha[ET];   // reused in-place for ex
__device__ float    g_out[NN * HH];
__device__ float    g_ce[2];

// ordered-uint encoding for float atomicMax (handles negatives, -inf)
__device__ __forceinline__ unsigned encf(float f) {
    unsigned u = __float_as_uint(f);
    return (u & 0x80000000u) ? ~u : (u | 0x80000000u);
}
__device__ __forceinline__ float decf(unsigned u) {
    return (u & 0x80000000u) ? __uint_as_float(u & 0x7FFFFFFFu)
                             : __uint_as_float(~u);
}
#define ENC_NEG_INF 0x007FFFFFu  // encf(-inf)

// ---------------- kernels ----------------

__global__ void k_init(const float* We1, const float* ae1,
                       const float* We2, const float* ae2) {
    int i = blockIdx.x * blockDim.x + threadIdx.x;
    if (i < NN) { g_sums[i] = 0.f; g_cnts[i] = 0.f; }
    if (i == 0) {
        float c = 0.f;
        for (int j = 0; j < HH; j++) c += We1[j] * ae1[j];
        g_ce[0] = c;
    }
    if (i == 1) {
        float c = 0.f;
        for (int j = 0; j < HH; j++) c += We2[j] * ae2[j];
        g_ce[1] = c;
    }
}

__global__ void k_seg(const int* __restrict__ dst, const float* __restrict__ ea) {
    int e = blockIdx.x * blockDim.x + threadIdx.x;
    if (e >= NE) return;
    int d = dst[e];
    atomicAdd(&g_sums[d], ea[e]);
    atomicAdd(&g_cnts[d], 1.f);
}

__global__ void k_loop() {
    int i = blockIdx.x * blockDim.x + threadIdx.x;
    if (i >= NN) return;
    g_loop[i] = g_sums[i] / fmaxf(g_cnts[i], 1.f);
    g_amax[i] = ENC_NEG_INF;
    g_den[i]  = 0.f;
}

// layer-1 node pass: x = emb[x_idx], h = x @ W1, hs = h.as1, hd = h.ad1; zero out
__global__ void k_h1(const int* __restrict__ x_idx, const float* __restrict__ emb,
                     const float* __restrict__ W1, const float* __restrict__ as1,
                     const float* __restrict__ ad1) {
    __shared__ float sW[EMBD * HH];
    __shared__ float sas[HH], sad[HH];
    int t = threadIdx.x;
    for (int i = t; i < EMBD * HH; i += blockDim.x) sW[i] = W1[i];
    if (t < HH) { sas[t] = as1[t]; sad[t] = ad1[t]; }
    __syncthreads();
    int n = (blockIdx.x * blockDim.x + t) >> 5;
    int lane = t & 31;
    if (n >= NN) return;
    int idx = x_idx[n];
    const float* xr = emb + idx * EMBD;
    float acc = 0.f;
#pragma unroll
    for (int k = 0; k < EMBD; k++) acc = fmaf(xr[k], sW[k * HH + lane], acc);
    g_h[n * HH + lane]   = acc;
    g_out[n * HH + lane] = 0.f;
    float s = acc * sas[lane];
    float d = acc * sad[lane];
    for (int o = 16; o; o >>= 1) {
        s += __shfl_xor_sync(0xffffffffu, s, o);
        d += __shfl_xor_sync(0xffffffffu, d, o);
    }
    if (lane == 0) { g_hs[n] = s; g_hd[n] = d; }
}

// per-edge alpha + segment max
__global__ void k_alpha(const int* __restrict__ src, const int* __restrict__ dst,
                        const float* __restrict__ ea, int layer) {
    int e = blockIdx.x * blockDim.x + threadIdx.x;
    if (e >= ET) return;
    int s, d; float a;
    if (e < NE) { s = src[e]; d = dst[e]; a = ea[e]; }
    else        { s = d = e - NE; a = g_loop[s]; }
    float al = g_hs[s] + g_hd[d] + a * g_ce[layer];
    al = (al > 0.f) ? al : 0.2f * al;
    g_alpha[e] = al;
    atomicMax(&g_amax[d], encf(al));
}

// per-edge exp + segment sum
__global__ void k_ex(const int* __restrict__ dst) {
    int e = blockIdx.x * blockDim.x + threadIdx.x;
    if (e >= ET) return;
    int d = (e < NE) ? dst[e] : (e - NE);
    float ex = __expf(g_alpha[e] - decf(g_amax[d]));
    g_alpha[e] = ex;
    atomicAdd(&g_den[d], ex);
}

// warp per edge: out[dst,:] += h[src,:] * coef
__global__ void k_scatter(const int* __restrict__ src, const int* __restrict__ dst) {
    int e = (blockIdx.x * blockDim.x + threadIdx.x) >> 5;
    if (e >= ET) return;
    int lane = threadIdx.x & 31;
    int s, d;
    if (e < NE) { s = src[e]; d = dst[e]; }
    else        { s = d = e - NE; }
    float coef = g_alpha[e] / (g_den[d] + 1e-16f);
    atomicAdd(&g_out[d * HH + lane], g_h[s * HH + lane] * coef);
}

// relu(out + b1) -> x2; h = x2 @ W2; hs/hd; reset amax/den; zero out
__global__ void k_mid(const float* __restrict__ b1, const float* __restrict__ W2,
                      const float* __restrict__ as2, const float* __restrict__ ad2) {
    __shared__ float sW[HH * HH];
    __shared__ float sb[HH], sas[HH], sad[HH];
    int t = threadIdx.x;
    for (int i = t; i < HH * HH; i += blockDim.x) sW[i] = W2[i];
    if (t < HH) { sb[t] = b1[t]; sas[t] = as2[t]; sad[t] = ad2[t]; }
    __syncthreads();
    int n = (blockIdx.x * blockDim.x + t) >> 5;
    int lane = t & 31;
    if (n >= NN) return;
    float v = fmaxf(g_out[n * HH + lane] + sb[lane], 0.f);
    g_out[n * HH + lane] = 0.f;
    float acc = 0.f;
#pragma unroll
    for (int k = 0; k < HH; k++)
        acc = fmaf(__shfl_sync(0xffffffffu, v, k), sW[k * HH + lane], acc);
    g_h[n * HH + lane] = acc;
    float s = acc * sas[lane];
    float d = acc * sad[lane];
    for (int o = 16; o; o >>= 1) {
        s += __shfl_xor_sync(0xffffffffu, s, o);
        d += __shfl_xor_sync(0xffffffffu, d, o);
    }
    if (lane == 0) {
        g_hs[n] = s; g_hd[n] = d;
        g_amax[n] = ENC_NEG_INF; g_den[n] = 0.f;
    }
}

// final: out[n] = bl + sum_j (g_out[n,j] + b2[j]) * Wl[j]
__global__ void k_final(const float* __restrict__ b2, const float* __restrict__ Wl,
                        const float* __restrict__ bl, float* __restrict__ out) {
    __shared__ float sb[HH], sw[HH];
    int t = threadIdx.x;
    if (t < HH) { sb[t] = b2[t]; sw[t] = Wl[t]; }
    __syncthreads();
    int n = (blockIdx.x * blockDim.x + t) >> 5;
    int lane = t & 31;
    if (n >= NN) return;
    float v = (g_out[n * HH + lane] + sb[lane]) * sw[lane];
    for (int o = 16; o; o >>= 1) v += __shfl_xor_sync(0xffffffffu, v, o);
    if (lane == 0) out[n] = v + bl[0];
}

// ---------------- launch ----------------
extern "C" void kernel_launch(void* const* d_in, const int* in_sizes, int n_in,
                              void* d_out, int out_size) {
    const int*   x_idx = (const int*)  d_in[0];
    const int*   ei    = (const int*)  d_in[1];
    const float* ea    = (const float*)d_in[2];
    const float* emb   = (const float*)d_in[3];
    const float* W1    = (const float*)d_in[4];
    const float* as1   = (const float*)d_in[5];
    const float* ad1   = (const float*)d_in[6];
    const float* We1   = (const float*)d_in[7];
    const float* ae1   = (const float*)d_in[8];
    const float* b1    = (const float*)d_in[9];
    const float* W2    = (const float*)d_in[10];
    const float* as2   = (const float*)d_in[11];
    const float* ad2   = (const float*)d_in[12];
    const float* We2   = (const float*)d_in[13];
    const float* ae2   = (const float*)d_in[14];
    const float* b2    = (const float*)d_in[15];
    const float* Wl    = (const float*)d_in[16];
    const float* bl    = (const float*)d_in[17];
    float* out = (float*)d_out;

    const int* src = ei;
    const int* dst = ei + NE;

    const int TB = 256;
    const int gN  = (NN + TB - 1) / TB;
    const int gE  = (NE + TB - 1) / TB;
    const int gET = (ET + TB - 1) / TB;
    const int gNW = (NN * 32 + TB - 1) / TB;                       // warp per node
    const int gSC = (int)(((long long)ET * 32 + TB - 1) / TB);     // warp per edge

    k_init<<<gN, TB>>>(We1, ae1, We2, ae2);
    k_seg<<<gE, TB>>>(dst, ea);
    k_loop<<<gN, TB>>>();

    // layer 1
    k_h1<<<gNW, TB>>>(x_idx, emb, W1, as1, ad1);
    k_alpha<<<gET, TB>>>(src, dst, ea, 0);
    k_ex<<<gET, TB>>>(dst);
    k_scatter<<<gSC, TB>>>(src, dst);

    // layer 2
    k_mid<<<gNW, TB>>>(b1, W2, as2, ad2);
    k_alpha<<<gET, TB>>>(src, dst, ea, 1);
    k_ex<<<gET, TB>>>(dst);
    k_scatter<<<gSC, TB>>>(src, dst);

    k_final<<<gNW, TB>>>(b2, Wl, bl, out);
}

// round 2
// speedup vs baseline: 2.2387x; 2.2387x over previous
#include <cuda_runtime.h>

#define NN 100000
#define NE 3200000
#define ET (NE + NN)
#define HH 32
#define EMBD 16

// ---------------- device scratch (static, no allocation) ----------------
__device__ float2   g_sc[NN];        // (sum, count) for self-loop attr
__device__ float    g_loop[NN];
__device__ float    g_h[NN * HH];
__device__ float    g_hs[NN];
__device__ float    g_hd[NN];
__device__ float    g_den[NN];
__device__ float    g_ex[ET];
__device__ float    g_out[NN * HH];
__device__ float    g_ce[2];

// ---------------- vector reduction helpers (sm_90+) ----------------
__device__ __forceinline__ void red_add_v4(float* p, float4 v) {
    asm volatile("red.global.add.v4.f32 [%0], {%1,%2,%3,%4};"
                 :: "l"(p), "f"(v.x), "f"(v.y), "f"(v.z), "f"(v.w) : "memory");
}
__device__ __forceinline__ void red_add_v2(float* p, float2 v) {
    asm volatile("red.global.add.v2.f32 [%0], {%1,%2};"
                 :: "l"(p), "f"(v.x), "f"(v.y) : "memory");
}

// ---------------- kernels ----------------

__global__ void k_init(const float* We1, const float* ae1,
                       const float* We2, const float* ae2) {
    int i = blockIdx.x * blockDim.x + threadIdx.x;
    if (i < NN) g_sc[i] = make_float2(0.f, 0.f);
    if (i == 0) {
        float c = 0.f;
        for (int j = 0; j < HH; j++) c += We1[j] * ae1[j];
        g_ce[0] = c;
    }
    if (i == 1) {
        float c = 0.f;
        for (int j = 0; j < HH; j++) c += We2[j] * ae2[j];
        g_ce[1] = c;
    }
}

__global__ void k_seg(const int* __restrict__ dst, const float* __restrict__ ea) {
    int e = blockIdx.x * blockDim.x + threadIdx.x;
    if (e >= NE) return;
    int d = dst[e];
    red_add_v2(&g_sc[d].x, make_float2(ea[e], 1.f));
}

__global__ void k_loop() {
    int i = blockIdx.x * blockDim.x + threadIdx.x;
    if (i >= NN) return;
    float2 sc = g_sc[i];
    g_loop[i] = sc.x / fmaxf(sc.y, 1.f);
    g_den[i]  = 0.f;
}

// layer-1 node pass: x = emb[x_idx], h = x @ W1, hs = h.as1, hd = h.ad1; zero out
__global__ void k_h1(const int* __restrict__ x_idx, const float* __restrict__ emb,
                     const float* __restrict__ W1, const float* __restrict__ as1,
                     const float* __restrict__ ad1) {
    __shared__ float sW[EMBD * HH];
    __shared__ float sas[HH], sad[HH];
    int t = threadIdx.x;
    for (int i = t; i < EMBD * HH; i += blockDim.x) sW[i] = W1[i];
    if (t < HH) { sas[t] = as1[t]; sad[t] = ad1[t]; }
    __syncthreads();
    int n = (blockIdx.x * blockDim.x + t) >> 5;
    int lane = t & 31;
    if (n >= NN) return;
    int idx = x_idx[n];
    const float* xr = emb + idx * EMBD;
    float acc = 0.f;
#pragma unroll
    for (int k = 0; k < EMBD; k++) acc = fmaf(xr[k], sW[k * HH + lane], acc);
    g_h[n * HH + lane]   = acc;
    g_out[n * HH + lane] = 0.f;
    float s = acc * sas[lane];
    float d = acc * sad[lane];
    for (int o = 16; o; o >>= 1) {
        s += __shfl_xor_sync(0xffffffffu, s, o);
        d += __shfl_xor_sync(0xffffffffu, d, o);
    }
    if (lane == 0) { g_hs[n] = s; g_hd[n] = d; }
}

// fused per-edge: alpha -> leaky_relu -> exp (unshifted, shift-invariant softmax)
// -> store ex, atomicAdd denom
__global__ void k_alphaex(const int* __restrict__ src, const int* __restrict__ dst,
                          const float* __restrict__ ea, int layer) {
    int e = blockIdx.x * blockDim.x + threadIdx.x;
    if (e >= ET) return;
    int s, d; float a;
    if (e < NE) { s = src[e]; d = dst[e]; a = ea[e]; }
    else        { s = d = e - NE; a = g_loop[s]; }
    float al = g_hs[s] + g_hd[d] + a * g_ce[layer];
    al = (al > 0.f) ? al : 0.2f * al;
    float ex = __expf(al);
    g_ex[e] = ex;
    atomicAdd(&g_den[d], ex);
}

// 8 lanes per edge, float4 gather + vector red: out[dst,:] += h[src,:] * coef
__global__ void k_scatter(const int* __restrict__ src, const int* __restrict__ dst) {
    long long t = (long long)blockIdx.x * blockDim.x + threadIdx.x;
    int e = (int)(t >> 3);
    if (e >= ET) return;
    int q = (int)(t & 7);
    int s, d;
    if (e < NE) { s = src[e]; d = dst[e]; }
    else        { s = d = e - NE; }
    float coef = g_ex[e] / (g_den[d] + 1e-16f);
    float4 hv = *reinterpret_cast<const float4*>(g_h + s * HH + q * 4);
    hv.x *= coef; hv.y *= coef; hv.z *= coef; hv.w *= coef;
    red_add_v4(g_out + d * HH + q * 4, hv);
}

// relu(out + b1) -> x2; h = x2 @ W2; hs/hd; reset den; zero out
__global__ void k_mid(const float* __restrict__ b1, const float* __restrict__ W2,
                      const float* __restrict__ as2, const float* __restrict__ ad2) {
    __shared__ float sW[HH * HH];
    __shared__ float sb[HH], sas[HH], sad[HH];
    int t = threadIdx.x;
    for (int i = t; i < HH * HH; i += blockDim.x) sW[i] = W2[i];
    if (t < HH) { sb[t] = b1[t]; sas[t] = as2[t]; sad[t] = ad2[t]; }
    __syncthreads();
    int n = (blockIdx.x * blockDim.x + t) >> 5;
    int lane = t & 31;
    if (n >= NN) return;
    float v = fmaxf(g_out[n * HH + lane] + sb[lane], 0.f);
    g_out[n * HH + lane] = 0.f;
    float acc = 0.f;
#pragma unroll
    for (int k = 0; k < HH; k++)
        acc = fmaf(__shfl_sync(0xffffffffu, v, k), sW[k * HH + lane], acc);
    g_h[n * HH + lane] = acc;
    float s = acc * sas[lane];
    float d = acc * sad[lane];
    for (int o = 16; o; o >>= 1) {
        s += __shfl_xor_sync(0xffffffffu, s, o);
        d += __shfl_xor_sync(0xffffffffu, d, o);
    }
    if (lane == 0) {
        g_hs[n] = s; g_hd[n] = d;
        g_den[n] = 0.f;
    }
}

// final: out[n] = bl + sum_j (g_out[n,j] + b2[j]) * Wl[j]
__global__ void k_final(const float* __restrict__ b2, const float* __restrict__ Wl,
                        const float* __restrict__ bl, float* __restrict__ out) {
    __shared__ float sb[HH], sw[HH];
    int t = threadIdx.x;
    if (t < HH) { sb[t] = b2[t]; sw[t] = Wl[t]; }
    __syncthreads();
    int n = (blockIdx.x * blockDim.x + t) >> 5;
    int lane = t & 31;
    if (n >= NN) return;
    float v = (g_out[n * HH + lane] + sb[lane]) * sw[lane];
    for (int o = 16; o; o >>= 1) v += __shfl_xor_sync(0xffffffffu, v, o);
    if (lane == 0) out[n] = v + bl[0];
}

// ---------------- launch ----------------
extern "C" void kernel_launch(void* const* d_in, const int* in_sizes, int n_in,
                              void* d_out, int out_size) {
    const int*   x_idx = (const int*)  d_in[0];
    const int*   ei    = (const int*)  d_in[1];
    const float* ea    = (const float*)d_in[2];
    const float* emb   = (const float*)d_in[3];
    const float* W1    = (const float*)d_in[4];
    const float* as1   = (const float*)d_in[5];
    const float* ad1   = (const float*)d_in[6];
    const float* We1   = (const float*)d_in[7];
    const float* ae1   = (const float*)d_in[8];
    const float* b1    = (const float*)d_in[9];
    const float* W2    = (const float*)d_in[10];
    const float* as2   = (const float*)d_in[11];
    const float* ad2   = (const float*)d_in[12];
    const float* We2   = (const float*)d_in[13];
    const float* ae2   = (const float*)d_in[14];
    const float* b2    = (const float*)d_in[15];
    const float* Wl    = (const float*)d_in[16];
    const float* bl    = (const float*)d_in[17];
    float* out = (float*)d_out;

    const int* src = ei;
    const int* dst = ei + NE;

    const int TB = 256;
    const int gN  = (NN + TB - 1) / TB;
    const int gE  = (NE + TB - 1) / TB;
    const int gET = (ET + TB - 1) / TB;
    const int gNW = (NN * 32 + TB - 1) / TB;                      // warp per node
    const int gSC = (int)(((long long)ET * 8 + TB - 1) / TB);     // 8 lanes per edge

    k_init<<<gN, TB>>>(We1, ae1, We2, ae2);
    k_seg<<<gE, TB>>>(dst, ea);
    k_loop<<<gN, TB>>>();

    // layer 1
    k_h1<<<gNW, TB>>>(x_idx, emb, W1, as1, ad1);
    k_alphaex<<<gET, TB>>>(src, dst, ea, 0);
    k_scatter<<<gSC, TB>>>(src, dst);

    // layer 2
    k_mid<<<gNW, TB>>>(b1, W2, as2, ad2);
    k_alphaex<<<gET, TB>>>(src, dst, ea, 1);
    k_scatter<<<gSC, TB>>>(src, dst);

    k_final<<<gNW, TB>>>(b2, Wl, bl, out);
}

// round 3
// speedup vs baseline: 2.8185x; 1.2590x over previous
#include <cuda_runtime.h>

#define NN 100000
#define NE 3200000
#define HH 32
#define EMBD 16

// ---------------- device scratch (static, no allocation) ----------------
__device__ float2   g_sc[NN];        // (sum, count) for self-loop attr
__device__ float    g_loop[NN];
__device__ float    g_h[NN * HH];
__device__ float    g_hs[NN];
__device__ float    g_hd[NN];
__device__ float    g_den[NN];
__device__ float    g_out[NN * HH];
__device__ float    g_ce[2];

// ---------------- vector reduction helpers (sm_90+) ----------------
__device__ __forceinline__ void red_add_v4(float* p, float4 v) {
    asm volatile("red.global.add.v4.f32 [%0], {%1,%2,%3,%4};"
                 :: "l"(p), "f"(v.x), "f"(v.y), "f"(v.z), "f"(v.w) : "memory");
}
__device__ __forceinline__ void red_add_v2(float* p, float2 v) {
    asm volatile("red.global.add.v2.f32 [%0], {%1,%2};"
                 :: "l"(p), "f"(v.x), "f"(v.y) : "memory");
}

// ---------------- kernels ----------------

__global__ void k_init(const float* We1, const float* ae1,
                       const float* We2, const float* ae2) {
    int i = blockIdx.x * blockDim.x + threadIdx.x;
    if (i < NN) g_sc[i] = make_float2(0.f, 0.f);
    if (i == 0) {
        float c = 0.f;
        for (int j = 0; j < HH; j++) c += We1[j] * ae1[j];
        g_ce[0] = c;
    }
    if (i == 1) {
        float c = 0.f;
        for (int j = 0; j < HH; j++) c += We2[j] * ae2[j];
        g_ce[1] = c;
    }
}

__global__ void k_seg(const int* __restrict__ dst, const float* __restrict__ ea) {
    int e = blockIdx.x * blockDim.x + threadIdx.x;
    if (e >= NE) return;
    int d = dst[e];
    red_add_v2(&g_sc[d].x, make_float2(ea[e], 1.f));
}

__global__ void k_loop() {
    int i = blockIdx.x * blockDim.x + threadIdx.x;
    if (i >= NN) return;
    float2 sc = g_sc[i];
    g_loop[i] = sc.x / fmaxf(sc.y, 1.f);
    g_den[i]  = 0.f;
}

// layer-1 node pass: x = emb[x_idx], h = x @ W1, hs = h.as1, hd = h.ad1; zero out
__global__ void k_h1(const int* __restrict__ x_idx, const float* __restrict__ emb,
                     const float* __restrict__ W1, const float* __restrict__ as1,
                     const float* __restrict__ ad1) {
    __shared__ float sW[EMBD * HH];
    __shared__ float sas[HH], sad[HH];
    int t = threadIdx.x;
    for (int i = t; i < EMBD * HH; i += blockDim.x) sW[i] = W1[i];
    if (t < HH) { sas[t] = as1[t]; sad[t] = ad1[t]; }
    __syncthreads();
    int n = (blockIdx.x * blockDim.x + t) >> 5;
    int lane = t & 31;
    if (n >= NN) return;
    int idx = x_idx[n];
    const float* xr = emb + idx * EMBD;
    float acc = 0.f;
#pragma unroll
    for (int k = 0; k < EMBD; k++) acc = fmaf(xr[k], sW[k * HH + lane], acc);
    g_h[n * HH + lane]   = acc;
    g_out[n * HH + lane] = 0.f;
    float s = acc * sas[lane];
    float d = acc * sad[lane];
    for (int o = 16; o; o >>= 1) {
        s += __shfl_xor_sync(0xffffffffu, s, o);
        d += __shfl_xor_sync(0xffffffffu, d, o);
    }
    if (lane == 0) { g_hs[n] = s; g_hd[n] = d; }
}

// SINGLE fused edge pass (real edges only): ex = exp(lrelu(alpha));
// out[dst,:] += ex * h[src,:]  (unnormalized),  den[dst] += ex.
// 8 lanes per edge, float4 gather + vector red.
__global__ void k_edge(const int* __restrict__ src, const int* __restrict__ dst,
                       const float* __restrict__ ea, int layer) {
    long long t = (long long)blockIdx.x * blockDim.x + threadIdx.x;
    int e = (int)(t >> 3);
    if (e >= NE) return;
    int q = (int)(t & 7);
    int s = src[e], d = dst[e];
    float al = g_hs[s] + g_hd[d] + ea[e] * g_ce[layer];
    al = (al > 0.f) ? al : 0.2f * al;
    float ex = __expf(al);
    float4 hv = *reinterpret_cast<const float4*>(g_h + s * HH + q * 4);
    hv.x *= ex; hv.y *= ex; hv.z *= ex; hv.w *= ex;
    red_add_v4(g_out + d * HH + q * 4, hv);
    if (q == 0) atomicAdd(&g_den[d], ex);
}

// normalize (+ self-loop term), relu(.+b1) -> x2; h = x2 @ W2; hs/hd; reset den; zero out
__global__ void k_mid(const float* __restrict__ b1, const float* __restrict__ W2,
                      const float* __restrict__ as2, const float* __restrict__ ad2) {
    __shared__ float sW[HH * HH];
    __shared__ float sb[HH], sas[HH], sad[HH];
    int t = threadIdx.x;
    for (int i = t; i < HH * HH; i += blockDim.x) sW[i] = W2[i];
    if (t < HH) { sb[t] = b1[t]; sas[t] = as2[t]; sad[t] = ad2[t]; }
    __syncthreads();
    int n = (blockIdx.x * blockDim.x + t) >> 5;
    int lane = t & 31;
    if (n >= NN) return;
    // self-loop edge term for layer 1
    float al = g_hs[n] + g_hd[n] + g_loop[n] * g_ce[0];
    al = (al > 0.f) ? al : 0.2f * al;
    float exs = __expf(al);
    float hn = g_h[n * HH + lane];
    float v = (g_out[n * HH + lane] + exs * hn) / (g_den[n] + exs + 1e-16f);
    v = fmaxf(v + sb[lane], 0.f);
    g_out[n * HH + lane] = 0.f;
    float acc = 0.f;
#pragma unroll
    for (int k = 0; k < HH; k++)
        acc = fmaf(__shfl_sync(0xffffffffu, v, k), sW[k * HH + lane], acc);
    g_h[n * HH + lane] = acc;
    float s = acc * sas[lane];
    float d = acc * sad[lane];
    for (int o = 16; o; o >>= 1) {
        s += __shfl_xor_sync(0xffffffffu, s, o);
        d += __shfl_xor_sync(0xffffffffu, d, o);
    }
    if (lane == 0) {
        g_hs[n] = s; g_hd[n] = d;
        g_den[n] = 0.f;
    }
}

// final: normalize (+ self-loop, layer 2), out[n] = bl + sum_j (v + b2[j]) * Wl[j]
__global__ void k_final(const float* __restrict__ b2, const float* __restrict__ Wl,
                        const float* __restrict__ bl, float* __restrict__ out) {
    __shared__ float sb[HH], sw[HH];
    int t = threadIdx.x;
    if (t < HH) { sb[t] = b2[t]; sw[t] = Wl[t]; }
    __syncthreads();
    int n = (blockIdx.x * blockDim.x + t) >> 5;
    int lane = t & 31;
    if (n >= NN) return;
    float al = g_hs[n] + g_hd[n] + g_loop[n] * g_ce[1];
    al = (al > 0.f) ? al : 0.2f * al;
    float exs = __expf(al);
    float hn = g_h[n * HH + lane];
    float v = (g_out[n * HH + lane] + exs * hn) / (g_den[n] + exs + 1e-16f);
    v = (v + sb[lane]) * sw[lane];
    for (int o = 16; o; o >>= 1) v += __shfl_xor_sync(0xffffffffu, v, o);
    if (lane == 0) out[n] = v + bl[0];
}

// ---------------- launch ----------------
extern "C" void kernel_launch(void* const* d_in, const int* in_sizes, int n_in,
                              void* d_out, int out_size) {
    const int*   x_idx = (const int*)  d_in[0];
    const int*   ei    = (const int*)  d_in[1];
    const float* ea    = (const float*)d_in[2];
    const float* emb   = (const float*)d_in[3];
    const float* W1    = (const float*)d_in[4];
    const float* as1   = (const float*)d_in[5];
    const float* ad1   = (const float*)d_in[6];
    const float* We1   = (const float*)d_in[7];
    const float* ae1   = (const float*)d_in[8];
    const float* b1    = (const float*)d_in[9];
    const float* W2    = (const float*)d_in[10];
    const float* as2   = (const float*)d_in[11];
    const float* ad2   = (const float*)d_in[12];
    const float* We2   = (const float*)d_in[13];
    const float* ae2   = (const float*)d_in[14];
    const float* b2    = (const float*)d_in[15];
    const float* Wl    = (const float*)d_in[16];
    const float* bl    = (const float*)d_in[17];
    float* out = (float*)d_out;

    const int* src = ei;
    const int* dst = ei + NE;

    const int TB = 256;
    const int gN  = (NN + TB - 1) / TB;
    const int gE  = (NE + TB - 1) / TB;
    const int gNW = (NN * 32 + TB - 1) / TB;                      // warp per node
    const int gED = (int)(((long long)NE * 8 + TB - 1) / TB);     // 8 lanes per edge

    k_init<<<gN, TB>>>(We1, ae1, We2, ae2);
    k_seg<<<gE, TB>>>(dst, ea);
    k_loop<<<gN, TB>>>();

    // layer 1
    k_h1<<<gNW, TB>>>(x_idx, emb, W1, as1, ad1);
    k_edge<<<gED, TB>>>(src, dst, ea, 0);

    // layer 2
    k_mid<<<gNW, TB>>>(b1, W2, as2, ad2);
    k_edge<<<gED, TB>>>(src, dst, ea, 1);

    k_final<<<gNW, TB>>>(b2, Wl, bl, out);
}

// round 4
// speedup vs baseline: 3.8697x; 1.3730x over previous
#include <cuda_runtime.h>

#define NN 100000
#define NE 3200000
#define HH 32
#define EMBD 16

// ---------------- device scratch (static, no allocation) ----------------
__device__ float2   g_sc[NN];        // (sum, count) for self-loop attr
__device__ float    g_h[NN * HH];    // layer-1 features
__device__ float    g_hs[NN];        // layer-1 h·as
__device__ float    g_hd[NN];        // layer-1 h·ad, reused for layer-2 h2·ad2
__device__ float    g_den[NN];       // layer-1 softmax denom
__device__ float    g_out[NN * HH];  // layer-1 unnormalized aggregation
__device__ float2   g_sp[NN];        // layer-2 (h2·as2, h2·Wl)
__device__ float2   g_acc2[NN];      // layer-2 (num, den) scalar accum
__device__ float    g_ce[3];         // ce1, ce2, b2·Wl + bl

// ---------------- vector reduction helpers (sm_90+) ----------------
__device__ __forceinline__ void red_add_v4(float* p, float4 v) {
    asm volatile("red.global.add.v4.f32 [%0], {%1,%2,%3,%4};"
                 :: "l"(p), "f"(v.x), "f"(v.y), "f"(v.z), "f"(v.w) : "memory");
}
__device__ __forceinline__ void red_add_v2(float* p, float2 v) {
    asm volatile("red.global.add.v2.f32 [%0], {%1,%2};"
                 :: "l"(p), "f"(v.x), "f"(v.y) : "memory");
}

// ---------------- kernels ----------------

__global__ void k_init(const float* We1, const float* ae1,
                       const float* We2, const float* ae2,
                       const float* b2,  const float* Wl, const float* bl) {
    int i = blockIdx.x * blockDim.x + threadIdx.x;
    if (i < NN) { g_sc[i] = make_float2(0.f, 0.f); g_den[i] = 0.f; }
    if (i == 0) {
        float c = 0.f;
        for (int j = 0; j < HH; j++) c += We1[j] * ae1[j];
        g_ce[0] = c;
    }
    if (i == 1) {
        float c = 0.f;
        for (int j = 0; j < HH; j++) c += We2[j] * ae2[j];
        g_ce[1] = c;
    }
    if (i == 2) {
        float c = bl[0];
        for (int j = 0; j < HH; j++) c += b2[j] * Wl[j];
        g_ce[2] = c;
    }
}

// layer-1 node pass: x = emb[x_idx], h = x @ W1, hs = h.as1, hd = h.ad1; zero out
__global__ void k_h1(const int* __restrict__ x_idx, const float* __restrict__ emb,
                     const float* __restrict__ W1, const float* __restrict__ as1,
                     const float* __restrict__ ad1) {
    __shared__ float sW[EMBD * HH];
    __shared__ float sas[HH], sad[HH];
    int t = threadIdx.x;
    for (int i = t; i < EMBD * HH; i += blockDim.x) sW[i] = W1[i];
    if (t < HH) { sas[t] = as1[t]; sad[t] = ad1[t]; }
    __syncthreads();
    int n = (blockIdx.x * blockDim.x + t) >> 5;
    int lane = t & 31;
    if (n >= NN) return;
    int idx = x_idx[n];
    const float* xr = emb + idx * EMBD;
    float acc = 0.f;
#pragma unroll
    for (int k = 0; k < EMBD; k++) acc = fmaf(xr[k], sW[k * HH + lane], acc);
    g_h[n * HH + lane]   = acc;
    g_out[n * HH + lane] = 0.f;
    float s = acc * sas[lane];
    float d = acc * sad[lane];
    for (int o = 16; o; o >>= 1) {
        s += __shfl_xor_sync(0xffffffffu, s, o);
        d += __shfl_xor_sync(0xffffffffu, d, o);
    }
    if (lane == 0) { g_hs[n] = s; g_hd[n] = d; }
}

// layer-1 fused edge pass (real edges only), 8 lanes/edge:
//   ex = exp(lrelu(hs[s]+hd[d]+ea*ce0))
//   out[d,:] += ex*h[s,:]  ;  den[d] += ex  ;  sc[d] += (ea, 1)  [self-loop stats]
__global__ void k_edge1(const int* __restrict__ src, const int* __restrict__ dst,
                        const float* __restrict__ ea) {
    long long t = (long long)blockIdx.x * blockDim.x + threadIdx.x;
    int e = (int)(t >> 3);
    if (e >= NE) return;
    int q = (int)(t & 7);
    int s = src[e], d = dst[e];
    float a = ea[e];
    float al = g_hs[s] + g_hd[d] + a * g_ce[0];
    al = (al > 0.f) ? al : 0.2f * al;
    float ex = __expf(al);
    float4 hv = *reinterpret_cast<const float4*>(g_h + s * HH + q * 4);
    hv.x *= ex; hv.y *= ex; hv.z *= ex; hv.w *= ex;
    red_add_v4(g_out + d * HH + q * 4, hv);
    if (q == 0) {
        atomicAdd(&g_den[d], ex);
        red_add_v2(&g_sc[d].x, make_float2(a, 1.f));
    }
}

// normalize layer 1 (+ self-loop), relu(.+b1); h2 = v @ W2;
// write sp = (h2.as2, h2.Wl), hd = h2.ad2, zero acc2
__global__ void k_mid(const float* __restrict__ b1, const float* __restrict__ W2,
                      const float* __restrict__ as2, const float* __restrict__ ad2,
                      const float* __restrict__ Wl) {
    __shared__ float sW[HH * HH];
    __shared__ float sb[HH], sas[HH], sad[HH], swl[HH];
    int t = threadIdx.x;
    for (int i = t; i < HH * HH; i += blockDim.x) sW[i] = W2[i];
    if (t < HH) { sb[t] = b1[t]; sas[t] = as2[t]; sad[t] = ad2[t]; swl[t] = Wl[t]; }
    __syncthreads();
    int n = (blockIdx.x * blockDim.x + t) >> 5;
    int lane = t & 31;
    if (n >= NN) return;
    // self-loop term for layer 1
    float2 sc = g_sc[n];
    float loop = sc.x / fmaxf(sc.y, 1.f);
    float al = g_hs[n] + g_hd[n] + loop * g_ce[0];
    al = (al > 0.f) ? al : 0.2f * al;
    float exs = __expf(al);
    float hn = g_h[n * HH + lane];
    float v = (g_out[n * HH + lane] + exs * hn) / (g_den[n] + exs + 1e-16f);
    v = fmaxf(v + sb[lane], 0.f);
    float acc = 0.f;
#pragma unroll
    for (int k = 0; k < HH; k++)
        acc = fmaf(__shfl_sync(0xffffffffu, v, k), sW[k * HH + lane], acc);
    float s = acc * sas[lane];
    float d = acc * sad[lane];
    float p = acc * swl[lane];
    for (int o = 16; o; o >>= 1) {
        s += __shfl_xor_sync(0xffffffffu, s, o);
        d += __shfl_xor_sync(0xffffffffu, d, o);
        p += __shfl_xor_sync(0xffffffffu, p, o);
    }
    if (lane == 0) {
        g_sp[n] = make_float2(s, p);
        g_hd[n] = d;
        g_acc2[n] = make_float2(0.f, 0.f);
    }
}

// layer-2 edge pass, 1 thread/edge (scalar projection trick):
//   ex = exp(lrelu(hs2[s]+hd2[d]+ea*ce1)); acc2[d] += (ex*p[s], ex)
__global__ void k_edge2(const int* __restrict__ src, const int* __restrict__ dst,
                        const float* __restrict__ ea) {
    int e = blockIdx.x * blockDim.x + threadIdx.x;
    if (e >= NE) return;
    int s = src[e], d = dst[e];
    float2 sp = g_sp[s];
    float al = sp.x + g_hd[d] + ea[e] * g_ce[1];
    al = (al > 0.f) ? al : 0.2f * al;
    float ex = __expf(al);
    red_add_v2(&g_acc2[d].x, make_float2(ex * sp.y, ex));
}

// final: add self-loop, normalize, add (b2·Wl + bl)
__global__ void k_final(float* __restrict__ out) {
    int n = blockIdx.x * blockDim.x + threadIdx.x;
    if (n >= NN) return;
    float2 sc = g_sc[n];
    float loop = sc.x / fmaxf(sc.y, 1.f);
    float2 sp = g_sp[n];
    float al = sp.x + g_hd[n] + loop * g_ce[1];
    al = (al > 0.f) ? al : 0.2f * al;
    float exs = __expf(al);
    float2 acc = g_acc2[n];
    out[n] = (acc.x + exs * sp.y) / (acc.y + exs + 1e-16f) + g_ce[2];
}

// ---------------- launch ----------------
extern "C" void kernel_launch(void* const* d_in, const int* in_sizes, int n_in,
                              void* d_out, int out_size) {
    const int*   x_idx = (const int*)  d_in[0];
    const int*   ei    = (const int*)  d_in[1];
    const float* ea    = (const float*)d_in[2];
    const float* emb   = (const float*)d_in[3];
    const float* W1    = (const float*)d_in[4];
    const float* as1   = (const float*)d_in[5];
    const float* ad1   = (const float*)d_in[6];
    const float* We1   = (const float*)d_in[7];
    const float* ae1   = (const float*)d_in[8];
    const float* b1    = (const float*)d_in[9];
    const float* W2    = (const float*)d_in[10];
    const float* as2   = (const float*)d_in[11];
    const float* ad2   = (const float*)d_in[12];
    const float* We2   = (const float*)d_in[13];
    const float* ae2   = (const float*)d_in[14];
    const float* b2    = (const float*)d_in[15];
    const float* Wl    = (const float*)d_in[16];
    const float* bl    = (const float*)d_in[17];
    float* out = (float*)d_out;

    const int* src = ei;
    const int* dst = ei + NE;

    const int TB = 256;
    const int gN   = (NN + TB - 1) / TB;
    const int gE   = (NE + TB - 1) / TB;
    const int gNW  = (NN * 32 + TB - 1) / TB;                     // warp per node
    const int gED1 = (int)(((long long)NE * 8 + TB - 1) / TB);    // 8 lanes per edge

    k_init<<<gN, TB>>>(We1, ae1, We2, ae2, b2, Wl, bl);

    // layer 1
    k_h1<<<gNW, TB>>>(x_idx, emb, W1, as1, ad1);
    k_edge1<<<gED1, TB>>>(src, dst, ea);

    // layer 2 (scalar-projected)
    k_mid<<<gNW, TB>>>(b1, W2, as2, ad2, Wl);
    k_edge2<<<gE, TB>>>(src, dst, ea);

    k_final<<<gN, TB>>>(out);
}

// round 5
// speedup vs baseline: 4.2947x; 1.1098x over previous
#include <cuda_runtime.h>
#include <cuda_fp16.h>

#define NN 100000
#define NE 3200000
#define HH 32
#define EMBD 16

// ---------------- device scratch (static, no allocation) ----------------
__device__ float2   g_sc[NN];         // (sum, count) for self-loop attr
__device__ __half   g_h[NN * HH];     // layer-1 features (fp16 storage)
__device__ float    g_hs[NN];         // layer-1 h·as
__device__ float    g_hd[NN];         // layer-1 h·ad, reused for layer-2 h2·ad2
__device__ float    g_den[NN];        // layer-1 softmax denom
__device__ float    g_out[NN * HH];   // layer-1 unnormalized aggregation (fp32 atomics)
__device__ float2   g_sp[NN];         // layer-2 (h2·as2, h2·Wl)
__device__ float2   g_acc2[NN];       // layer-2 (num, den) scalar accum
__device__ float    g_ce[3];          // ce1, ce2, b2·Wl + bl
__device__ float    g_cs[HH];         // W2 · as2
__device__ float    g_cd[HH];         // W2 · ad2
__device__ float    g_cp[HH];         // W2 · Wl

// ---------------- vector reduction helpers (sm_90+) ----------------
__device__ __forceinline__ void red_add_v4(float* p, float4 v) {
    asm volatile("red.global.add.v4.f32 [%0], {%1,%2,%3,%4};"
                 :: "l"(p), "f"(v.x), "f"(v.y), "f"(v.z), "f"(v.w) : "memory");
}
__device__ __forceinline__ void red_add_v2(float* p, float2 v) {
    asm volatile("red.global.add.v2.f32 [%0], {%1,%2};"
                 :: "l"(p), "f"(v.x), "f"(v.y) : "memory");
}

// ---------------- kernels ----------------

__global__ void k_init(const float* We1, const float* ae1,
                       const float* We2, const float* ae2,
                       const float* b2,  const float* Wl, const float* bl,
                       const float* W2,  const float* as2, const float* ad2) {
    int i = blockIdx.x * blockDim.x + threadIdx.x;
    if (i < NN) { g_sc[i] = make_float2(0.f, 0.f); g_den[i] = 0.f; }
    if (i == 0) {
        float c = 0.f;
        for (int j = 0; j < HH; j++) c += We1[j] * ae1[j];
        g_ce[0] = c;
    }
    if (i == 1) {
        float c = 0.f;
        for (int j = 0; j < HH; j++) c += We2[j] * ae2[j];
        g_ce[1] = c;
    }
    if (i == 2) {
        float c = bl[0];
        for (int j = 0; j < HH; j++) c += b2[j] * Wl[j];
        g_ce[2] = c;
    }
    // collapsed layer-2 projection vectors: cX[k] = sum_j W2[k][j] * X[j]
    if (blockIdx.x == 1 && threadIdx.x < HH) {
        int k = threadIdx.x;
        float cs = 0.f, cd = 0.f, cp = 0.f;
        const float* wr = W2 + k * HH;
        for (int j = 0; j < HH; j++) {
            float w = wr[j];
            cs = fmaf(w, as2[j], cs);
            cd = fmaf(w, ad2[j], cd);
            cp = fmaf(w, Wl[j],  cp);
        }
        g_cs[k] = cs; g_cd[k] = cd; g_cp[k] = cp;
    }
}

// layer-1 node pass: x = emb[x_idx], h = x @ W1 (store fp16), hs/hd; zero out
__global__ void k_h1(const int* __restrict__ x_idx, const float* __restrict__ emb,
                     const float* __restrict__ W1, const float* __restrict__ as1,
                     const float* __restrict__ ad1) {
    __shared__ float sW[EMBD * HH];
    __shared__ float sas[HH], sad[HH];
    int t = threadIdx.x;
    for (int i = t; i < EMBD * HH; i += blockDim.x) sW[i] = W1[i];
    if (t < HH) { sas[t] = as1[t]; sad[t] = ad1[t]; }
    __syncthreads();
    int n = (blockIdx.x * blockDim.x + t) >> 5;
    int lane = t & 31;
    if (n >= NN) return;
    int idx = x_idx[n];
    const float* xr = emb + idx * EMBD;
    float acc = 0.f;
#pragma unroll
    for (int k = 0; k < EMBD; k++) acc = fmaf(xr[k], sW[k * HH + lane], acc);
    g_h[n * HH + lane]   = __float2half(acc);
    g_out[n * HH + lane] = 0.f;
    float s = acc * sas[lane];
    float d = acc * sad[lane];
    for (int o = 16; o; o >>= 1) {
        s += __shfl_xor_sync(0xffffffffu, s, o);
        d += __shfl_xor_sync(0xffffffffu, d, o);
    }
    if (lane == 0) { g_hs[n] = s; g_hd[n] = d; }
}

// layer-1 fused edge pass (real edges only), 8 lanes/edge:
//   ex = exp(lrelu(hs[s]+hd[d]+ea*ce0))
//   out[d,:] += ex*h[s,:]  ;  den[d] += ex  ;  sc[d] += (ea, 1)
__global__ void k_edge1(const int* __restrict__ src, const int* __restrict__ dst,
                        const float* __restrict__ ea) {
    long long t = (long long)blockIdx.x * blockDim.x + threadIdx.x;
    int e = (int)(t >> 3);
    if (e >= NE) return;
    int q = (int)(t & 7);
    int s = src[e], d = dst[e];
    float a = ea[e];
    float al = g_hs[s] + g_hd[d] + a * g_ce[0];
    al = (al > 0.f) ? al : 0.2f * al;
    float ex = __expf(al);
    // gather 4 fp16 features (8 bytes)
    const __half2* hp = reinterpret_cast<const __half2*>(g_h + s * HH + q * 4);
    float2 h01 = __half22float2(hp[0]);
    float2 h23 = __half22float2(hp[1]);
    float4 hv = make_float4(h01.x * ex, h01.y * ex, h23.x * ex, h23.y * ex);
    red_add_v4(g_out + d * HH + q * 4, hv);
    if (q == 0) {
        atomicAdd(&g_den[d], ex);
        red_add_v2(&g_sc[d].x, make_float2(a, 1.f));
    }
}

// normalize layer 1 (+ self-loop), relu(.+b1); collapsed layer-2 projections:
// s = cs·v, d = cd·v, p = cp·v  (no GEMV needed)
__global__ void k_mid(const float* __restrict__ b1) {
    int t = threadIdx.x;
    int n = (blockIdx.x * blockDim.x + t) >> 5;
    int lane = t & 31;
    if (n >= NN) return;
    float2 sc = g_sc[n];
    float loop = sc.x / fmaxf(sc.y, 1.f);
    float al = g_hs[n] + g_hd[n] + loop * g_ce[0];
    al = (al > 0.f) ? al : 0.2f * al;
    float exs = __expf(al);
    float hn = __half2float(g_h[n * HH + lane]);
    float v = (g_out[n * HH + lane] + exs * hn) / (g_den[n] + exs + 1e-16f);
    v = fmaxf(v + b1[lane], 0.f);
    float s = v * g_cs[lane];
    float d = v * g_cd[lane];
    float p = v * g_cp[lane];
    for (int o = 16; o; o >>= 1) {
        s += __shfl_xor_sync(0xffffffffu, s, o);
        d += __shfl_xor_sync(0xffffffffu, d, o);
        p += __shfl_xor_sync(0xffffffffu, p, o);
    }
    if (lane == 0) {
        g_sp[n] = make_float2(s, p);
        g_hd[n] = d;
        g_acc2[n] = make_float2(0.f, 0.f);
    }
}

// layer-2 edge pass, 1 thread/edge (scalar projection):
//   ex = exp(lrelu(hs2[s]+hd2[d]+ea*ce1)); acc2[d] += (ex*p[s], ex)
__global__ void k_edge2(const int* __restrict__ src, const int* __restrict__ dst,
                        const float* __restrict__ ea) {
    int e = blockIdx.x * blockDim.x + threadIdx.x;
    if (e >= NE) return;
    int s = src[e], d = dst[e];
    float2 sp = g_sp[s];
    float al = sp.x + g_hd[d] + ea[e] * g_ce[1];
    al = (al > 0.f) ? al : 0.2f * al;
    float ex = __expf(al);
    red_add_v2(&g_acc2[d].x, make_float2(ex * sp.y, ex));
}

// final: add self-loop, normalize, add (b2·Wl + bl)
__global__ void k_final(float* __restrict__ out) {
    int n = blockIdx.x * blockDim.x + threadIdx.x;
    if (n >= NN) return;
    float2 sc = g_sc[n];
    float loop = sc.x / fmaxf(sc.y, 1.f);
    float2 sp = g_sp[n];
    float al = sp.x + g_hd[n] + loop * g_ce[1];
    al = (al > 0.f) ? al : 0.2f * al;
    float exs = __expf(al);
    float2 acc = g_acc2[n];
    out[n] = (acc.x + exs * sp.y) / (acc.y + exs + 1e-16f) + g_ce[2];
}

// ---------------- launch ----------------
extern "C" void kernel_launch(void* const* d_in, const int* in_sizes, int n_in,
                              void* d_out, int out_size) {
    const int*   x_idx = (const int*)  d_in[0];
    const int*   ei    = (const int*)  d_in[1];
    const float* ea    = (const float*)d_in[2];
    const float* emb   = (const float*)d_in[3];
    const float* W1    = (const float*)d_in[4];
    const float* as1   = (const float*)d_in[5];
    const float* ad1   = (const float*)d_in[6];
    const float* We1   = (const float*)d_in[7];
    const float* ae1   = (const float*)d_in[8];
    const float* b1    = (const float*)d_in[9];
    const float* W2    = (const float*)d_in[10];
    const float* as2   = (const float*)d_in[11];
    const float* ad2   = (const float*)d_in[12];
    const float* We2   = (const float*)d_in[13];
    const float* ae2   = (const float*)d_in[14];
    const float* b2    = (const float*)d_in[15];
    const float* Wl    = (const float*)d_in[16];
    const float* bl    = (const float*)d_in[17];
    float* out = (float*)d_out;

    const int* src = ei;
    const int* dst = ei + NE;

    const int TB = 256;
    const int gN   = (NN + TB - 1) / TB;
    const int gE   = (NE + TB - 1) / TB;
    const int gNW  = (NN * 32 + TB - 1) / TB;                     // warp per node
    const int gED1 = (int)(((long long)NE * 8 + TB - 1) / TB);    // 8 lanes per edge

    k_init<<<gN, TB>>>(We1, ae1, We2, ae2, b2, Wl, bl, W2, as2, ad2);

    // layer 1
    k_h1<<<gNW, TB>>>(x_idx, emb, W1, as1, ad1);
    k_edge1<<<gED1, TB>>>(src, dst, ea);

    // layer 2 (collapsed to scalar projections)
    k_mid<<<gNW, TB>>>(b1);
    k_edge2<<<gE, TB>>>(src, dst, ea);

    k_final<<<gN, TB>>>(out);
}

// round 6
// speedup vs baseline: 4.3243x; 1.0069x over previous
#include <cuda_runtime.h>
#include <cuda_fp16.h>

#define NN 100000
#define NE 3200000
#define HH 32
#define OS 36   // g_out row stride: [32 feats | den, sc_sum, sc_cnt, pad]

// ---------------- device scratch (static, no allocation) ----------------
__device__ __half   g_h[NN * HH];     // layer-1 features (fp16 storage)
__device__ float    g_hs[NN];         // layer-1 h·as
__device__ float    g_hd[NN];         // layer-1 h·ad, reused for layer-2 h2·ad2
__device__ float    g_out[NN * OS];   // layer-1 agg + [den, sc.x, sc.y, pad]
__device__ float2   g_sp[NN];         // layer-2 (h2·as2, h2·Wl)
__device__ float2   g_acc2[NN];       // layer-2 (num, den) scalar accum
__device__ float    g_ce[3];          // ce1, ce2, b2·Wl + bl
__device__ float    g_cs[HH];         // W2 · as2
__device__ float    g_cd[HH];         // W2 · ad2
__device__ float    g_cp[HH];         // W2 · Wl

#define EMBD 16

// ---------------- vector reduction helpers (sm_90+) ----------------
__device__ __forceinline__ void red_add_v4(float* p, float4 v) {
    asm volatile("red.global.add.v4.f32 [%0], {%1,%2,%3,%4};"
                 :: "l"(p), "f"(v.x), "f"(v.y), "f"(v.z), "f"(v.w) : "memory");
}
__device__ __forceinline__ void red_add_v2(float* p, float2 v) {
    asm volatile("red.global.add.v2.f32 [%0], {%1,%2};"
                 :: "l"(p), "f"(v.x), "f"(v.y) : "memory");
}

// ---------------- kernels ----------------

__global__ void k_init(const float* We1, const float* ae1,
                       const float* We2, const float* ae2,
                       const float* b2,  const float* Wl, const float* bl,
                       const float* W2,  const float* as2, const float* ad2) {
    int i = blockIdx.x * blockDim.x + threadIdx.x;
    if (i == 0) {
        float c = 0.f;
        for (int j = 0; j < HH; j++) c += We1[j] * ae1[j];
        g_ce[0] = c;
    }
    if (i == 1) {
        float c = 0.f;
        for (int j = 0; j < HH; j++) c += We2[j] * ae2[j];
        g_ce[1] = c;
    }
    if (i == 2) {
        float c = bl[0];
        for (int j = 0; j < HH; j++) c += b2[j] * Wl[j];
        g_ce[2] = c;
    }
    // collapsed layer-2 projection vectors: cX[k] = sum_j W2[k][j] * X[j]
    if (i >= 32 && i < 32 + HH) {
        int k = i - 32;
        float cs = 0.f, cd = 0.f, cp = 0.f;
        const float* wr = W2 + k * HH;
        for (int j = 0; j < HH; j++) {
            float w = wr[j];
            cs = fmaf(w, as2[j], cs);
            cd = fmaf(w, ad2[j], cd);
            cp = fmaf(w, Wl[j],  cp);
        }
        g_cs[k] = cs; g_cd[k] = cd; g_cp[k] = cp;
    }
}

// layer-1 node pass: x = emb[x_idx], h = x @ W1 (store fp16), hs/hd; zero out-row
__global__ void k_h1(const int* __restrict__ x_idx, const float* __restrict__ emb,
                     const float* __restrict__ W1, const float* __restrict__ as1,
                     const float* __restrict__ ad1) {
    __shared__ float sW[EMBD * HH];
    __shared__ float sas[HH], sad[HH];
    int t = threadIdx.x;
    for (int i = t; i < EMBD * HH; i += blockDim.x) sW[i] = W1[i];
    if (t < HH) { sas[t] = as1[t]; sad[t] = ad1[t]; }
    __syncthreads();
    int n = (blockIdx.x * blockDim.x + t) >> 5;
    int lane = t & 31;
    if (n >= NN) return;
    int idx = x_idx[n];
    const float* xr = emb + idx * EMBD;
    float acc = 0.f;
#pragma unroll
    for (int k = 0; k < EMBD; k++) acc = fmaf(xr[k], sW[k * HH + lane], acc);
    g_h[n * HH + lane] = __float2half(acc);
    g_out[n * OS + lane] = 0.f;
    if (lane < OS - 32) g_out[n * OS + 32 + lane] = 0.f;
    float s = acc * sas[lane];
    float d = acc * sad[lane];
    for (int o = 16; o; o >>= 1) {
        s += __shfl_xor_sync(0xffffffffu, s, o);
        d += __shfl_xor_sync(0xffffffffu, d, o);
    }
    if (lane == 0) { g_hs[n] = s; g_hd[n] = d; }
}

// layer-1 fused edge pass, 8 lanes/edge; ex computed once per edge (lane q==0):
//   out[d,0:32] += ex*h[s,:]  ;  out[d,32:36] += (ex, ea, 1, 0)
__global__ void k_edge1(const int* __restrict__ src, const int* __restrict__ dst,
                        const float* __restrict__ ea) {
    long long t = (long long)blockIdx.x * blockDim.x + threadIdx.x;
    int e = (int)(t >> 3);
    if (e >= NE) return;
    int lane = threadIdx.x & 31;
    int q = lane & 7;
    int s = src[e], d = dst[e];
    float ex;
    if (q == 0) {
        float a = ea[e];
        float al = g_hs[s] + g_hd[d] + a * g_ce[0];
        al = (al > 0.f) ? al : 0.2f * al;
        ex = __expf(al);
        red_add_v4(g_out + d * OS + 32, make_float4(ex, a, 1.f, 0.f));
    }
    // grid is an exact multiple: all 32 lanes alive -> full-mask shfl is safe
    ex = __shfl_sync(0xffffffffu, ex, lane & ~7);
    const __half2* hp = reinterpret_cast<const __half2*>(g_h + s * HH + q * 4);
    float2 h01 = __half22float2(hp[0]);
    float2 h23 = __half22float2(hp[1]);
    float4 hv = make_float4(h01.x * ex, h01.y * ex, h23.x * ex, h23.y * ex);
    red_add_v4(g_out + d * OS + q * 4, hv);
}

// normalize layer 1 (+ self-loop), relu(.+b1); collapsed layer-2 projections
__global__ void k_mid(const float* __restrict__ b1) {
    int t = threadIdx.x;
    int n = (blockIdx.x * blockDim.x + t) >> 5;
    int lane = t & 31;
    if (n >= NN) return;
    float4 aux = make_float4(0.f, 0.f, 0.f, 0.f);
    if (lane == 0)
        aux = *reinterpret_cast<const float4*>(g_out + n * OS + 32);
    float den  = __shfl_sync(0xffffffffu, aux.x, 0);
    float scx  = __shfl_sync(0xffffffffu, aux.y, 0);
    float scc  = __shfl_sync(0xffffffffu, aux.z, 0);
    float loop = scx / fmaxf(scc, 1.f);
    float al = g_hs[n] + g_hd[n] + loop * g_ce[0];
    al = (al > 0.f) ? al : 0.2f * al;
    float exs = __expf(al);
    float hn = __half2float(g_h[n * HH + lane]);
    float v = (g_out[n * OS + lane] + exs * hn) / (den + exs + 1e-16f);
    v = fmaxf(v + b1[lane], 0.f);
    float s = v * g_cs[lane];
    float d = v * g_cd[lane];
    float p = v * g_cp[lane];
    for (int o = 16; o; o >>= 1) {
        s += __shfl_xor_sync(0xffffffffu, s, o);
        d += __shfl_xor_sync(0xffffffffu, d, o);
        p += __shfl_xor_sync(0xffffffffu, p, o);
    }
    if (lane == 0) {
        g_sp[n] = make_float2(s, p);
        g_hd[n] = d;
        g_acc2[n] = make_float2(0.f, 0.f);
    }
}

// layer-2 edge pass, 1 thread/edge (scalar projection):
//   ex = exp(lrelu(hs2[s]+hd2[d]+ea*ce1)); acc2[d] += (ex*p[s], ex)
__global__ void k_edge2(const int* __restrict__ src, const int* __restrict__ dst,
                        const float* __restrict__ ea) {
    int e = blockIdx.x * blockDim.x + threadIdx.x;
    if (e >= NE) return;
    int s = src[e], d = dst[e];
    float2 sp = g_sp[s];
    float al = sp.x + g_hd[d] + ea[e] * g_ce[1];
    al = (al > 0.f) ? al : 0.2f * al;
    float ex = __expf(al);
    red_add_v2(&g_acc2[d].x, make_float2(ex * sp.y, ex));
}

// final: add self-loop, normalize, add (b2·Wl + bl)
__global__ void k_final(float* __restrict__ out) {
    int n = blockIdx.x * blockDim.x + threadIdx.x;
    if (n >= NN) return;
    float4 aux = *reinterpret_cast<const float4*>(g_out + n * OS + 32);
    float loop = aux.y / fmaxf(aux.z, 1.f);
    float2 sp = g_sp[n];
    float al = sp.x + g_hd[n] + loop * g_ce[1];
    al = (al > 0.f) ? al : 0.2f * al;
    float exs = __expf(al);
    float2 acc = g_acc2[n];
    out[n] = (acc.x + exs * sp.y) / (acc.y + exs + 1e-16f) + g_ce[2];
}

// ---------------- launch ----------------
extern "C" void kernel_launch(void* const* d_in, const int* in_sizes, int n_in,
                              void* d_out, int out_size) {
    const int*   x_idx = (const int*)  d_in[0];
    const int*   ei    = (const int*)  d_in[1];
    const float* ea    = (const float*)d_in[2];
    const float* emb   = (const float*)d_in[3];
    const float* W1    = (const float*)d_in[4];
    const float* as1   = (const float*)d_in[5];
    const float* ad1   = (const float*)d_in[6];
    const float* We1   = (const float*)d_in[7];
    const float* ae1   = (const float*)d_in[8];
    const float* b1    = (const float*)d_in[9];
    const float* W2    = (const float*)d_in[10];
    const float* as2   = (const float*)d_in[11];
    const float* ad2   = (const float*)d_in[12];
    const float* We2   = (const float*)d_in[13];
    const float* ae2   = (const float*)d_in[14];
    const float* b2    = (const float*)d_in[15];
    const float* Wl    = (const float*)d_in[16];
    const float* bl    = (const float*)d_in[17];
    float* out = (float*)d_out;

    const int* src = ei;
    const int* dst = ei + NE;

    const int TB = 256;
    const int gN   = (NN + TB - 1) / TB;
    const int gE   = (NE + TB - 1) / TB;
    const int gNW  = (NN * 32 + TB - 1) / TB;                     // warp per node
    const int gED1 = (int)(((long long)NE * 8 + TB - 1) / TB);    // 8 lanes per edge

    k_init<<<1, 64>>>(We1, ae1, We2, ae2, b2, Wl, bl, W2, as2, ad2);

    // layer 1
    k_h1<<<gNW, TB>>>(x_idx, emb, W1, as1, ad1);
    k_edge1<<<gED1, TB>>>(src, dst, ea);

    // layer 2 (collapsed to scalar projections)
    k_mid<<<gNW, TB>>>(b1);
    k_edge2<<<gE, TB>>>(src, dst, ea);

    k_final<<<gN, TB>>>(out);
}